// round 9
// baseline (speedup 1.0000x reference)
#include <cuda_runtime.h>
#include <cuda_bf16.h>
#include <math.h>
#include <stdint.h>

// ---------------------------------------------------------------- shapes
#define M_TOTAL 4096
#define K_DIM   1024
#define N_VOCAB 32000
#define NBITS   15
#define KB      4096            // K' bytes per row: [hi|.|.|lo] digit products
#define BM      128
#define BN      128
#define NKI     32              // KB / 128
#define NT2     1000

#define STAGE   32768           // 16KB A + 16KB B (128 rows x 128B each)
#define NSTAGE  4
#define DSMEM   (NSTAGE * STAGE + 128)

// ---------------------------------------------------------------- scratch
__device__ int8_t g_A8[(size_t)M_TOTAL * KB];    // [A1 | A1 | A0 | A0]
__device__ int8_t g_B8[(size_t)N_VOCAB * KB];    // [B1 | B0 | B1 | B0]
__device__ float  g_sA[M_TOTAL];
__device__ float  g_sB[N_VOCAB];
__device__ float  g_pmax[M_TOTAL * NT2];
__device__ float  g_psum[M_TOTAL * NT2];
__device__ float  g_pnum[(size_t)M_TOTAL * NT2 * 5];

// ---------------------------------------------------------------- helpers
__device__ __forceinline__ uint32_t smem_u32(const void* p) {
    uint32_t a;
    asm("{ .reg .u64 t; cvta.to.shared.u64 t, %1; cvt.u32.u64 %0, t; }" : "=r"(a) : "l"(p));
    return a;
}
__device__ __forceinline__ void cp_async16(uint32_t dst, const void* src) {
    asm volatile("cp.async.cg.shared.global [%0], [%1], 16;" :: "r"(dst), "l"(src) : "memory");
}
__device__ __forceinline__ void cp_commit() {
    asm volatile("cp.async.commit_group;" ::: "memory");
}
template <int N>
__device__ __forceinline__ void cp_wait() {
    asm volatile("cp.async.wait_group %0;" :: "n"(N) : "memory");
}
__device__ __forceinline__ void ldsm_x4(uint32_t* r, uint32_t addr) {
    asm volatile("ldmatrix.sync.aligned.m8n8.x4.shared.b16 {%0,%1,%2,%3}, [%4];"
                 : "=r"(r[0]), "=r"(r[1]), "=r"(r[2]), "=r"(r[3]) : "r"(addr));
}
__device__ __forceinline__ void mma_s8(int* c, const uint32_t* a, const uint32_t* b) {
    asm volatile("mma.sync.aligned.m16n8k32.row.col.s32.s8.s8.s32 "
                 "{%0,%1,%2,%3}, {%4,%5,%6,%7}, {%8,%9}, {%0,%1,%2,%3};"
                 : "+r"(c[0]), "+r"(c[1]), "+r"(c[2]), "+r"(c[3])
                 : "r"(a[0]), "r"(a[1]), "r"(a[2]), "r"(a[3]), "r"(b[0]), "r"(b[1]));
}
#define SWZ(off) ((off) ^ (((off) >> 3) & 0x70))

// ---------------------------------------------------------------- quantization
// row -> alpha*(hi*256 + lo), hi/lo int8, alpha = rowmax/32639
template <bool IS_B>
__global__ void quant_kernel(const float* __restrict__ src, int8_t* __restrict__ dst,
                             float* __restrict__ scale) {
    __shared__ float s_red[8];
    const int row = blockIdx.x;
    const int tid = threadIdx.x;
    const int col = tid * 4;

    float4 v = *(const float4*)(src + (size_t)row * K_DIM + col);
    float m = fmaxf(fmaxf(fabsf(v.x), fabsf(v.y)), fmaxf(fabsf(v.z), fabsf(v.w)));
#pragma unroll
    for (int o = 16; o >= 1; o >>= 1)
        m = fmaxf(m, __shfl_xor_sync(0xffffffffu, m, o));
    if ((tid & 31) == 0) s_red[tid >> 5] = m;
    __syncthreads();
    if (tid < 32) {
        float t = (tid < 8) ? s_red[tid] : 0.f;
#pragma unroll
        for (int o = 4; o >= 1; o >>= 1)
            t = fmaxf(t, __shfl_xor_sync(0xffffffffu, t, o));
        if (tid == 0) s_red[0] = t;
    }
    __syncthreads();
    float rowmax = s_red[0];
    float inva = (rowmax > 0.f) ? (32639.f / rowmax) : 0.f;
    if (tid == 0) scale[row] = (rowmax > 0.f) ? (rowmax / 32639.f) : 0.f;

    int q0 = __float2int_rn(v.x * inva);
    int q1 = __float2int_rn(v.y * inva);
    int q2 = __float2int_rn(v.z * inva);
    int q3 = __float2int_rn(v.w * inva);
    int h0 = (q0 + 128) >> 8, h1 = (q1 + 128) >> 8, h2 = (q2 + 128) >> 8, h3 = (q3 + 128) >> 8;
    int l0 = q0 - (h0 << 8), l1 = q1 - (h1 << 8), l2 = q2 - (h2 << 8), l3 = q3 - (h3 << 8);
    uint32_t ph = (h0 & 255) | ((h1 & 255) << 8) | ((h2 & 255) << 16) | ((h3 & 255) << 24);
    uint32_t pl = (l0 & 255) | ((l1 & 255) << 8) | ((l2 & 255) << 16) | ((l3 & 255) << 24);

    char* base = (char*)dst + (size_t)row * KB;
    if (IS_B) {   // [B1 | B0 | B1 | B0]
        *(uint32_t*)(base + col)        = ph;
        *(uint32_t*)(base + 1024 + col) = pl;
        *(uint32_t*)(base + 2048 + col) = ph;
        *(uint32_t*)(base + 3072 + col) = pl;
    } else {      // [A1 | A1 | A0 | A0]
        *(uint32_t*)(base + col)        = ph;
        *(uint32_t*)(base + 1024 + col) = ph;
        *(uint32_t*)(base + 2048 + col) = pl;
        *(uint32_t*)(base + 3072 + col) = pl;
    }
}

// ---------------------------------------------------------------- emb kernel
__global__ void emb_kernel(const int* __restrict__ ids,
                           const float* __restrict__ weight,
                           const float* __restrict__ weight_bit,
                           float* __restrict__ id_emb,
                           float* __restrict__ bit_emb) {
    int bs = blockIdx.x;
    int id = ids[bs];
    id = min(max(id, 0), N_VOCAB - 1);
    int d = threadIdx.x * 4;

    float4 w = *(const float4*)(weight + (size_t)id * K_DIM + d);
    *(float4*)(id_emb + (size_t)bs * K_DIM + d) = w;

    float4 acc = make_float4(0.f, 0.f, 0.f, 0.f);
#pragma unroll
    for (int k = 0; k < NBITS; k++) {
        float s = ((id >> (NBITS - 1 - k)) & 1) ? 1.0f : -1.0f;
        float4 wb = *(const float4*)(weight_bit + k * K_DIM + d);
        acc.x += s * wb.x; acc.y += s * wb.y; acc.z += s * wb.z; acc.w += s * wb.w;
    }
    *(float4*)(bit_emb + (size_t)bs * K_DIM + d) = acc;
}

// ---------------------------------------------------------------- GEMM (s8 IMMA)
__device__ __forceinline__ void load_stage(uint32_t sA, int m0, int n0, int kb, int tid) {
    uint32_t sB = sA + 16384;
#pragma unroll
    for (int u = 0; u < 4; ++u) {
        int seg = tid + u * 256;
        int row = seg >> 3, c = seg & 7;
        uint32_t off = row * 128 + c * 16;
        cp_async16(sA + SWZ(off), (const char*)g_A8 + (size_t)(m0 + row) * KB + kb * 128 + c * 16);
    }
#pragma unroll
    for (int u = 0; u < 4; ++u) {
        int seg = tid + u * 256;
        int row = seg >> 3, c = seg & 7;
        uint32_t off = row * 128 + c * 16;
        cp_async16(sB + SWZ(off), (const char*)g_B8 + (size_t)(n0 + row) * KB + kb * 128 + c * 16);
    }
}

__global__ void __launch_bounds__(256, 1)
gemm_mma_kernel(float* __restrict__ logit) {
    extern __shared__ char dynsmem[];
    const int tid = threadIdx.x;
    const int lane = tid & 31;
    const int wid = tid >> 5;
    const int warp_m = wid >> 2;        // 0..1 (64 rows)
    const int warp_n = wid & 3;         // 0..3 (32 cols)
    const int m0 = blockIdx.x * BM;     // m fastest -> B reuse in L2
    const int n0 = blockIdx.y * BN;

    uint32_t tile0 = (smem_u32(dynsmem) + 127) & ~127u;

    const int g  = lane >> 3;
    const int r8 = lane & 7;
    const int a_row = warp_m * 64 + ((g & 1) << 3) + r8;
    const int a_u   = g >> 1;
    const int b_row = warp_n * 32 + ((g >> 1) << 3) + r8;
    const int b_u   = g & 1;

    int   accS[4][4][4];
    float accF[4][4][4];
#pragma unroll
    for (int i = 0; i < 4; i++)
#pragma unroll
        for (int j = 0; j < 4; j++)
#pragma unroll
            for (int q = 0; q < 4; q++) { accS[i][j][q] = 0; accF[i][j][q] = 0.f; }

    load_stage(tile0 + 0 * STAGE, m0, n0, 0, tid); cp_commit();
    load_stage(tile0 + 1 * STAGE, m0, n0, 1, tid); cp_commit();
    load_stage(tile0 + 2 * STAGE, m0, n0, 2, tid); cp_commit();

#pragma unroll 1
    for (int kt = 0; kt < NKI; ++kt) {
        cp_wait<2>();
        __syncthreads();

        int kn = kt + 3;
        if (kn < NKI) load_stage(tile0 + (kn % NSTAGE) * STAGE, m0, n0, kn, tid);
        cp_commit();

        uint32_t sA = tile0 + (kt % NSTAGE) * STAGE;
        uint32_t sB = sA + 16384;

#pragma unroll
        for (int ks = 0; ks < 4; ++ks) {       // four k32 steps per 128B chunk
            uint32_t af[4][4];
            uint32_t bf[4][2];
#pragma unroll
            for (int i = 0; i < 4; ++i) {
                uint32_t off = (uint32_t)(a_row + i * 16) * 128 + (ks * 2 + a_u) * 16;
                ldsm_x4(af[i], sA + SWZ(off));
            }
            {
                uint32_t off0 = (uint32_t)(b_row) * 128 + (ks * 2 + b_u) * 16;
                ldsm_x4(&bf[0][0], sB + SWZ(off0));
                uint32_t off1 = (uint32_t)(b_row + 16) * 128 + (ks * 2 + b_u) * 16;
                ldsm_x4(&bf[2][0], sB + SWZ(off1));
            }
#pragma unroll
            for (int i = 0; i < 4; ++i)
#pragma unroll
                for (int j = 0; j < 4; ++j)
                    mma_s8(accS[i][j], af[i], bf[j]);
        }

        // Horner folds at digit-segment boundaries (kt = 7,15,23,31):
        // total = ((S_hihi*256 + S_hilo + S_lohi)*256) + S_lolo
        if ((kt & 7) == 7) {
            float sc = (kt == 7 || kt == 23) ? 256.f : 1.f;
#pragma unroll
            for (int i = 0; i < 4; ++i)
#pragma unroll
                for (int j = 0; j < 4; ++j)
#pragma unroll
                    for (int q = 0; q < 4; ++q) {
                        accF[i][j][q] = (accF[i][j][q] + (float)accS[i][j][q]) * sc;
                        accS[i][j][q] = 0;
                    }
        }
    }

    // ---------------- epilogue: scale, store logits, fused softmax partials
    const int n_base = n0 + warp_n * 32;
    const int t32 = n_base >> 5;

    float sB0[4], sB1[4];
#pragma unroll
    for (int j = 0; j < 4; ++j) {
        int n = n_base + j * 8 + (lane & 3) * 2;
        sB0[j] = g_sB[n];
        sB1[j] = g_sB[n + 1];
    }

#pragma unroll
    for (int i = 0; i < 4; ++i) {
#pragma unroll
        for (int half = 0; half < 2; ++half) {
            const int gm = m0 + warp_m * 64 + i * 16 + (lane >> 2) + half * 8;
            const float sA = g_sA[gm];
            float v[8];
#pragma unroll
            for (int j = 0; j < 4; ++j) {
                v[2 * j]     = sA * sB0[j] * accF[i][j][half * 2];
                v[2 * j + 1] = sA * sB1[j] * accF[i][j][half * 2 + 1];
            }
            float* p = logit + (size_t)gm * N_VOCAB + n_base;
#pragma unroll
            for (int j = 0; j < 4; ++j)
                *(float2*)(p + j * 8 + (lane & 3) * 2) = make_float2(v[2 * j], v[2 * j + 1]);

            float mx = v[0];
#pragma unroll
            for (int q = 1; q < 8; ++q) mx = fmaxf(mx, v[q]);
            mx = fmaxf(mx, __shfl_xor_sync(0xffffffffu, mx, 1));
            mx = fmaxf(mx, __shfl_xor_sync(0xffffffffu, mx, 2));

            float S = 0.f, b0 = 0.f, b3 = 0.f, b4 = 0.f;
#pragma unroll
            for (int j = 0; j < 4; ++j) {
                float e0 = __expf(v[2 * j] - mx);
                float e1 = __expf(v[2 * j + 1] - mx);
                float s2 = e0 + e1;
                S += s2;
                b0 += e1;
                if (j & 1) b3 += s2;
                if (j & 2) b4 += s2;
            }
            float b1 = (lane & 1) ? S : 0.f;
            float b2 = (lane & 2) ? S : 0.f;

#pragma unroll
            for (int o = 1; o <= 2; o <<= 1) {
                S  += __shfl_xor_sync(0xffffffffu, S, o);
                b0 += __shfl_xor_sync(0xffffffffu, b0, o);
                b1 += __shfl_xor_sync(0xffffffffu, b1, o);
                b2 += __shfl_xor_sync(0xffffffffu, b2, o);
                b3 += __shfl_xor_sync(0xffffffffu, b3, o);
                b4 += __shfl_xor_sync(0xffffffffu, b4, o);
            }

            if ((lane & 3) == 0) {
                int idx = gm * NT2 + t32;
                g_pmax[idx] = mx;
                g_psum[idx] = S;
                float* pn = g_pnum + (size_t)idx * 5;
                pn[0] = b4; pn[1] = b3; pn[2] = b2; pn[3] = b1; pn[4] = b0;
            }
        }
    }
}

// ---------------------------------------------------------------- reduce
__global__ void reduce_kernel(float* __restrict__ logit_w) {
    int row = blockIdx.x;
    int lane = threadIdx.x;

    float lmax = -3.402823466e38f;
    for (int t = lane; t < NT2; t += 32)
        lmax = fmaxf(lmax, g_pmax[row * NT2 + t]);
#pragma unroll
    for (int o = 16; o >= 1; o >>= 1)
        lmax = fmaxf(lmax, __shfl_xor_sync(0xffffffffu, lmax, o));

    float tot = 0.f;
    float num[NBITS];
#pragma unroll
    for (int k = 0; k < NBITS; k++) num[k] = 0.f;

    for (int t = lane; t < NT2; t += 32) {
        int idx = row * NT2 + t;
        float w = __expf(g_pmax[idx] - lmax);
        float Sw = g_psum[idx] * w;
        tot += Sw;
        int vb = t << 5;
#pragma unroll
        for (int k = 0; k < 10; k++)
            if ((vb >> (14 - k)) & 1) num[k] += Sw;
        const float* pn = g_pnum + (size_t)idx * 5;
        num[10] += pn[0] * w;
        num[11] += pn[1] * w;
        num[12] += pn[2] * w;
        num[13] += pn[3] * w;
        num[14] += pn[4] * w;
    }
#pragma unroll
    for (int o = 16; o >= 1; o >>= 1) {
        tot += __shfl_xor_sync(0xffffffffu, tot, o);
#pragma unroll
        for (int k = 0; k < NBITS; k++)
            num[k] += __shfl_xor_sync(0xffffffffu, num[k], o);
    }

    if (lane == 0) {
#pragma unroll
        for (int k = 0; k < NBITS; k++)
            logit_w[row * NBITS + k] = (2.f * num[k] - tot) / tot;
    }
}

// ---------------------------------------------------------------- launch
extern "C" void kernel_launch(void* const* d_in, const int* in_sizes, int n_in,
                              void* d_out, int out_size) {
    const int*   ids        = (const int*)d_in[0];
    const float* tensor     = (const float*)d_in[1];
    const float* weight     = (const float*)d_in[2];
    const float* weight_bit = (const float*)d_in[3];

    float* out     = (float*)d_out;
    float* id_emb  = out;
    float* bit_emb = out + 4194304;
    float* logit   = out + 8388608;
    float* logit_w = out + 8388608 + 131072000;

    cudaFuncSetAttribute(gemm_mma_kernel, cudaFuncAttributeMaxDynamicSharedMemorySize, DSMEM);

    int8_t* dA; cudaGetSymbolAddress((void**)&dA, g_A8);
    int8_t* dB; cudaGetSymbolAddress((void**)&dB, g_B8);
    float*  sA; cudaGetSymbolAddress((void**)&sA, g_sA);
    float*  sB; cudaGetSymbolAddress((void**)&sB, g_sB);

    quant_kernel<false><<<M_TOTAL, 256>>>(tensor, dA, sA);
    quant_kernel<true ><<<N_VOCAB, 256>>>(weight, dB, sB);
    emb_kernel<<<M_TOTAL, 256>>>(ids, weight, weight_bit, id_emb, bit_emb);
    gemm_mma_kernel<<<dim3(M_TOTAL / BM, N_VOCAB / BN), 256, DSMEM>>>(logit);
    reduce_kernel<<<M_TOTAL, 32>>>(logit_w);
}

// round 10
// speedup vs baseline: 5.8491x; 5.8491x over previous
#include <cuda_runtime.h>
#include <cuda_bf16.h>
#include <math.h>
#include <stdint.h>

// ---------------------------------------------------------------- shapes
#define M_TOTAL 4096
#define K_DIM   1024
#define N_VOCAB 32000
#define NBITS   15
#define KP      3072            // K' = 3*K (bf16 split-3 concatenated)
#define BM      128
#define BN      128
#define NKI     48              // KP / 64
#define NT2     1000            // 32-wide partial tiles per row
#define NTILES_M 32
#define NTILES  8000            // 32 * 250
#define GRID_P  296             // 2 CTAs per SM * 148

#define STAGE   32768           // 16KB A + 16KB B
#define NSTAGE  3
#define DSMEM   (NSTAGE * STAGE + 128)

// ---------------------------------------------------------------- scratch
__device__ __nv_bfloat16 g_A2[(size_t)M_TOTAL * KP];   // [Ah | Ah | Al]
__device__ __nv_bfloat16 g_B2[(size_t)N_VOCAB * KP];   // [Bh | Bl | Bh]
__device__ float g_pmax[M_TOTAL * NT2];
__device__ float g_psum[M_TOTAL * NT2];
__device__ float g_pnum[(size_t)M_TOTAL * NT2 * 5];

// ---------------------------------------------------------------- helpers
__device__ __forceinline__ uint32_t smem_u32(const void* p) {
    uint32_t a;
    asm("{ .reg .u64 t; cvta.to.shared.u64 t, %1; cvt.u32.u64 %0, t; }" : "=r"(a) : "l"(p));
    return a;
}
__device__ __forceinline__ void cp_async16(uint32_t dst, const void* src) {
    asm volatile("cp.async.cg.shared.global [%0], [%1], 16;" :: "r"(dst), "l"(src) : "memory");
}
__device__ __forceinline__ void cp_commit() {
    asm volatile("cp.async.commit_group;" ::: "memory");
}
template <int N>
__device__ __forceinline__ void cp_wait() {
    asm volatile("cp.async.wait_group %0;" :: "n"(N) : "memory");
}
__device__ __forceinline__ void ldsm_x4(uint32_t* r, uint32_t addr) {
    asm volatile("ldmatrix.sync.aligned.m8n8.x4.shared.b16 {%0,%1,%2,%3}, [%4];"
                 : "=r"(r[0]), "=r"(r[1]), "=r"(r[2]), "=r"(r[3]) : "r"(addr));
}
__device__ __forceinline__ void mma_bf16(float* c, const uint32_t* a, const uint32_t* b) {
    asm volatile("mma.sync.aligned.m16n8k16.row.col.f32.bf16.bf16.f32 "
                 "{%0,%1,%2,%3}, {%4,%5,%6,%7}, {%8,%9}, {%0,%1,%2,%3};"
                 : "+f"(c[0]), "+f"(c[1]), "+f"(c[2]), "+f"(c[3])
                 : "r"(a[0]), "r"(a[1]), "r"(a[2]), "r"(a[3]), "r"(b[0]), "r"(b[1]));
}
#define SWZ(off) ((off) ^ (((off) >> 3) & 0x70))

// ---------------------------------------------------------------- converters
__device__ __forceinline__ uint32_t pack_bf2(__nv_bfloat16 lo, __nv_bfloat16 hi) {
    return (uint32_t)__bfloat16_as_ushort(lo) | ((uint32_t)__bfloat16_as_ushort(hi) << 16);
}

__global__ void convertW_kernel(const float* __restrict__ W) {
    size_t i = ((size_t)blockIdx.x * 256 + threadIdx.x) * 4;
    int row = (int)(i >> 10);
    int col = (int)(i & 1023);
    float4 w = *(const float4*)(W + i);
    __nv_bfloat16 h0 = __float2bfloat16_rn(w.x), h1 = __float2bfloat16_rn(w.y);
    __nv_bfloat16 h2 = __float2bfloat16_rn(w.z), h3 = __float2bfloat16_rn(w.w);
    __nv_bfloat16 l0 = __float2bfloat16_rn(w.x - __bfloat162float(h0));
    __nv_bfloat16 l1 = __float2bfloat16_rn(w.y - __bfloat162float(h1));
    __nv_bfloat16 l2 = __float2bfloat16_rn(w.z - __bfloat162float(h2));
    __nv_bfloat16 l3 = __float2bfloat16_rn(w.w - __bfloat162float(h3));
    uint2 hi = make_uint2(pack_bf2(h0, h1), pack_bf2(h2, h3));
    uint2 lo = make_uint2(pack_bf2(l0, l1), pack_bf2(l2, l3));
    char* base = (char*)g_B2 + ((size_t)row * KP) * 2;
    *(uint2*)(base + (size_t)(col) * 2)        = hi;  // Bh
    *(uint2*)(base + (size_t)(1024 + col) * 2) = lo;  // Bl
    *(uint2*)(base + (size_t)(2048 + col) * 2) = hi;  // Bh
}

__global__ void convertA_kernel(const float* __restrict__ A) {
    size_t i = ((size_t)blockIdx.x * 256 + threadIdx.x) * 4;
    int row = (int)(i >> 10);
    int col = (int)(i & 1023);
    float4 w = *(const float4*)(A + i);
    __nv_bfloat16 h0 = __float2bfloat16_rn(w.x), h1 = __float2bfloat16_rn(w.y);
    __nv_bfloat16 h2 = __float2bfloat16_rn(w.z), h3 = __float2bfloat16_rn(w.w);
    __nv_bfloat16 l0 = __float2bfloat16_rn(w.x - __bfloat162float(h0));
    __nv_bfloat16 l1 = __float2bfloat16_rn(w.y - __bfloat162float(h1));
    __nv_bfloat16 l2 = __float2bfloat16_rn(w.z - __bfloat162float(h2));
    __nv_bfloat16 l3 = __float2bfloat16_rn(w.w - __bfloat16_as_ushort(h3) * 0.f - __bfloat162float(h3));
    uint2 hi = make_uint2(pack_bf2(h0, h1), pack_bf2(h2, h3));
    uint2 lo = make_uint2(pack_bf2(l0, l1), pack_bf2(l2, l3));
    char* base = (char*)g_A2 + ((size_t)row * KP) * 2;
    *(uint2*)(base + (size_t)(col) * 2)        = hi;  // Ah
    *(uint2*)(base + (size_t)(1024 + col) * 2) = hi;  // Ah
    *(uint2*)(base + (size_t)(2048 + col) * 2) = lo;  // Al
}

// ---------------------------------------------------------------- emb kernel
__global__ void emb_kernel(const int* __restrict__ ids,
                           const float* __restrict__ weight,
                           const float* __restrict__ weight_bit,
                           float* __restrict__ id_emb,
                           float* __restrict__ bit_emb) {
    int bs = blockIdx.x;
    int id = ids[bs];
    id = min(max(id, 0), N_VOCAB - 1);
    int d = threadIdx.x * 4;

    float4 w = *(const float4*)(weight + (size_t)id * K_DIM + d);
    *(float4*)(id_emb + (size_t)bs * K_DIM + d) = w;

    float4 acc = make_float4(0.f, 0.f, 0.f, 0.f);
#pragma unroll
    for (int k = 0; k < NBITS; k++) {
        float s = ((id >> (NBITS - 1 - k)) & 1) ? 1.0f : -1.0f;
        float4 wb = *(const float4*)(weight_bit + k * K_DIM + d);
        acc.x += s * wb.x; acc.y += s * wb.y; acc.z += s * wb.z; acc.w += s * wb.w;
    }
    *(float4*)(bit_emb + (size_t)bs * K_DIM + d) = acc;
}

// ---------------------------------------------------------------- GEMM (persistent)
__device__ __forceinline__ void load_stage(uint32_t sA, int tile, int kb, int tid) {
    const int m0 = (tile & (NTILES_M - 1)) * BM;
    const int n0 = (tile / NTILES_M) * BN;
    uint32_t sB = sA + 16384;
#pragma unroll
    for (int u = 0; u < 4; ++u) {
        int seg = tid + u * 256;
        int row = seg >> 3, c = seg & 7;
        uint32_t off = row * 128 + c * 16;
        cp_async16(sA + SWZ(off),
                   (const char*)g_A2 + ((size_t)(m0 + row) * KP + kb * 64 + c * 8) * 2);
    }
#pragma unroll
    for (int u = 0; u < 4; ++u) {
        int seg = tid + u * 256;
        int row = seg >> 3, c = seg & 7;
        uint32_t off = row * 128 + c * 16;
        cp_async16(sB + SWZ(off),
                   (const char*)g_B2 + ((size_t)(n0 + row) * KP + kb * 64 + c * 8) * 2);
    }
}

__global__ void __launch_bounds__(256, 2)
gemm_mma_kernel(float* __restrict__ logit) {
    extern __shared__ char dynsmem[];
    const int tid = threadIdx.x;
    const int lane = tid & 31;
    const int wid = tid >> 5;
    const int warp_m = wid >> 2;        // 0..1 (64 rows)
    const int warp_n = wid & 3;         // 0..3 (32 cols)
    const int G = gridDim.x;

    uint32_t tile0 = (smem_u32(dynsmem) + 127) & ~127u;

    // ldmatrix per-lane addressing
    const int a_row   = warp_m * 64 + (lane & 15);
    const int a_chunk = lane >> 4;
    const int bg      = lane >> 3;
    const int b_row   = warp_n * 32 + ((bg >> 1) << 3) + (lane & 7);
    const int b_chunk = bg & 1;

    // producer state (runs ahead by 2 chunks, crossing tile boundaries)
    int pt = blockIdx.x;
    int pk = 0;
    int pstage = 0;
#pragma unroll
    for (int i = 0; i < 2; ++i) {
        if (pt < NTILES) load_stage(tile0 + pstage * STAGE, pt, pk, tid);
        cp_commit();
        pstage = (pstage + 1 == NSTAGE) ? 0 : pstage + 1;
        if (++pk == NKI) { pk = 0; pt += G; }
    }

    int cstage = 0;
    for (int ct = blockIdx.x; ct < NTILES; ct += G) {
        float acc[4][4][4];
#pragma unroll
        for (int i = 0; i < 4; i++)
#pragma unroll
            for (int j = 0; j < 4; j++)
#pragma unroll
                for (int q = 0; q < 4; q++) acc[i][j][q] = 0.f;

#pragma unroll 1
        for (int kt = 0; kt < NKI; ++kt) {
            cp_wait<1>();
            __syncthreads();

            if (pt < NTILES) load_stage(tile0 + pstage * STAGE, pt, pk, tid);
            cp_commit();
            pstage = (pstage + 1 == NSTAGE) ? 0 : pstage + 1;
            if (++pk == NKI) { pk = 0; pt += G; }

            uint32_t sA = tile0 + cstage * STAGE;
            uint32_t sB = sA + 16384;
            cstage = (cstage + 1 == NSTAGE) ? 0 : cstage + 1;

#pragma unroll
            for (int ks = 0; ks < 4; ++ks) {
                uint32_t af[4][4];
                uint32_t bf[2][4];
#pragma unroll
                for (int i = 0; i < 4; ++i) {
                    uint32_t off = (uint32_t)(a_row + i * 16) * 128 + (ks * 2 + a_chunk) * 16;
                    ldsm_x4(af[i], sA + SWZ(off));
                }
#pragma unroll
                for (int j = 0; j < 2; ++j) {
                    uint32_t off = (uint32_t)(b_row + j * 16) * 128 + (ks * 2 + b_chunk) * 16;
                    ldsm_x4(bf[j], sB + SWZ(off));
                }
#pragma unroll
                for (int i = 0; i < 4; ++i)
#pragma unroll
                    for (int jj = 0; jj < 4; ++jj)
                        mma_bf16(acc[i][jj], af[i], &bf[jj >> 1][(jj & 1) * 2]);
            }
        }

        // ------------ epilogue for tile ct (loads for next tile already in flight)
        const int m0 = (ct & (NTILES_M - 1)) * BM;
        const int n0 = (ct / NTILES_M) * BN;
        const int n_base = n0 + warp_n * 32;
        const int t32 = n_base >> 5;

#pragma unroll
        for (int i = 0; i < 4; ++i) {
#pragma unroll
            for (int half = 0; half < 2; ++half) {
                const int gm = m0 + warp_m * 64 + i * 16 + (lane >> 2) + half * 8;
                float v[8];
#pragma unroll
                for (int j = 0; j < 4; ++j) {
                    v[2 * j]     = acc[i][j][half * 2];
                    v[2 * j + 1] = acc[i][j][half * 2 + 1];
                }
                float* p = logit + (size_t)gm * N_VOCAB + n_base;
#pragma unroll
                for (int j = 0; j < 4; ++j)
                    *(float2*)(p + j * 8 + (lane & 3) * 2) = make_float2(v[2 * j], v[2 * j + 1]);

                float mx = v[0];
#pragma unroll
                for (int q = 1; q < 8; ++q) mx = fmaxf(mx, v[q]);
                mx = fmaxf(mx, __shfl_xor_sync(0xffffffffu, mx, 1));
                mx = fmaxf(mx, __shfl_xor_sync(0xffffffffu, mx, 2));

                float S = 0.f, b0 = 0.f, b3 = 0.f, b4 = 0.f;
#pragma unroll
                for (int j = 0; j < 4; ++j) {
                    float e0 = __expf(v[2 * j] - mx);
                    float e1 = __expf(v[2 * j + 1] - mx);
                    float s2 = e0 + e1;
                    S += s2;
                    b0 += e1;
                    if (j & 1) b3 += s2;
                    if (j & 2) b4 += s2;
                }
                float b1 = (lane & 1) ? S : 0.f;
                float b2 = (lane & 2) ? S : 0.f;

#pragma unroll
                for (int o = 1; o <= 2; o <<= 1) {
                    S  += __shfl_xor_sync(0xffffffffu, S, o);
                    b0 += __shfl_xor_sync(0xffffffffu, b0, o);
                    b1 += __shfl_xor_sync(0xffffffffu, b1, o);
                    b2 += __shfl_xor_sync(0xffffffffu, b2, o);
                    b3 += __shfl_xor_sync(0xffffffffu, b3, o);
                    b4 += __shfl_xor_sync(0xffffffffu, b4, o);
                }

                if ((lane & 3) == 0) {
                    int idx = gm * NT2 + t32;
                    g_pmax[idx] = mx;
                    g_psum[idx] = S;
                    float* pn = g_pnum + (size_t)idx * 5;
                    pn[0] = b4; pn[1] = b3; pn[2] = b2; pn[3] = b1; pn[4] = b0;
                }
            }
        }
    }
}

// ---------------------------------------------------------------- reduce
__global__ void reduce_kernel(float* __restrict__ logit_w) {
    int row = blockIdx.x;
    int lane = threadIdx.x;

    float lmax = -3.402823466e38f;
    for (int t = lane; t < NT2; t += 32)
        lmax = fmaxf(lmax, g_pmax[row * NT2 + t]);
#pragma unroll
    for (int o = 16; o >= 1; o >>= 1)
        lmax = fmaxf(lmax, __shfl_xor_sync(0xffffffffu, lmax, o));

    float tot = 0.f;
    float num[NBITS];
#pragma unroll
    for (int k = 0; k < NBITS; k++) num[k] = 0.f;

    for (int t = lane; t < NT2; t += 32) {
        int idx = row * NT2 + t;
        float w = __expf(g_pmax[idx] - lmax);
        float Sw = g_psum[idx] * w;
        tot += Sw;
        int vb = t << 5;
#pragma unroll
        for (int k = 0; k < 10; k++)
            if ((vb >> (14 - k)) & 1) num[k] += Sw;
        const float* pn = g_pnum + (size_t)idx * 5;
        num[10] += pn[0] * w;
        num[11] += pn[1] * w;
        num[12] += pn[2] * w;
        num[13] += pn[3] * w;
        num[14] += pn[4] * w;
    }
#pragma unroll
    for (int o = 16; o >= 1; o >>= 1) {
        tot += __shfl_xor_sync(0xffffffffu, tot, o);
#pragma unroll
        for (int k = 0; k < NBITS; k++)
            num[k] += __shfl_xor_sync(0xffffffffu, num[k], o);
    }

    if (lane == 0) {
#pragma unroll
        for (int k = 0; k < NBITS; k++)
            logit_w[row * NBITS + k] = (2.f * num[k] - tot) / tot;
    }
}

// ---------------------------------------------------------------- launch
extern "C" void kernel_launch(void* const* d_in, const int* in_sizes, int n_in,
                              void* d_out, int out_size) {
    const int*   ids        = (const int*)d_in[0];
    const float* tensor     = (const float*)d_in[1];
    const float* weight     = (const float*)d_in[2];
    const float* weight_bit = (const float*)d_in[3];

    float* out     = (float*)d_out;
    float* id_emb  = out;
    float* bit_emb = out + 4194304;
    float* logit   = out + 8388608;
    float* logit_w = out + 8388608 + 131072000;

    cudaFuncSetAttribute(gemm_mma_kernel, cudaFuncAttributeMaxDynamicSharedMemorySize, DSMEM);

    convertA_kernel<<<4096, 256>>>(tensor);
    convertW_kernel<<<32000, 256>>>(weight);
    emb_kernel<<<M_TOTAL, 256>>>(ids, weight, weight_bit, id_emb, bit_emb);
    gemm_mma_kernel<<<GRID_P, 256, DSMEM>>>(logit);
    reduce_kernel<<<M_TOTAL, 32>>>(logit_w);
}

// round 11
// speedup vs baseline: 5.9041x; 1.0094x over previous
#include <cuda_runtime.h>
#include <cuda_bf16.h>
#include <math.h>
#include <stdint.h>

// ---------------------------------------------------------------- shapes
#define M_TOTAL 4096
#define K_DIM   1024
#define N_VOCAB 32000
#define NBITS   15
#define KP      3072            // K' = 3*K (bf16 split-3 concatenated)
#define BM      128
#define BN      256
#define NKI     48              // KP / 64
#define NT64    500             // 64-wide partial tiles per row

#define STAGE   49152           // 16KB A + 32KB B
#define NSTAGE  4
#define DSMEM   (NSTAGE * STAGE + 128)

// ---------------------------------------------------------------- scratch
__device__ __nv_bfloat16 g_A2[(size_t)M_TOTAL * KP];   // [Ah | Ah | Al]
__device__ __nv_bfloat16 g_B2[(size_t)N_VOCAB * KP];   // [Bh | Bl | Bh]
__device__ float g_pmax[M_TOTAL * NT64];
__device__ float g_psum[M_TOTAL * NT64];
__device__ float g_pnum[(size_t)M_TOTAL * NT64 * 6];

// ---------------------------------------------------------------- helpers
__device__ __forceinline__ uint32_t smem_u32(const void* p) {
    uint32_t a;
    asm("{ .reg .u64 t; cvta.to.shared.u64 t, %1; cvt.u32.u64 %0, t; }" : "=r"(a) : "l"(p));
    return a;
}
__device__ __forceinline__ void cp_async16(uint32_t dst, const void* src) {
    asm volatile("cp.async.cg.shared.global [%0], [%1], 16;" :: "r"(dst), "l"(src) : "memory");
}
__device__ __forceinline__ void cp_commit() {
    asm volatile("cp.async.commit_group;" ::: "memory");
}
template <int N>
__device__ __forceinline__ void cp_wait() {
    asm volatile("cp.async.wait_group %0;" :: "n"(N) : "memory");
}
__device__ __forceinline__ void ldsm_x4(uint32_t* r, uint32_t addr) {
    asm volatile("ldmatrix.sync.aligned.m8n8.x4.shared.b16 {%0,%1,%2,%3}, [%4];"
                 : "=r"(r[0]), "=r"(r[1]), "=r"(r[2]), "=r"(r[3]) : "r"(addr));
}
__device__ __forceinline__ void mma_bf16(float* c, const uint32_t* a, const uint32_t* b) {
    asm volatile("mma.sync.aligned.m16n8k16.row.col.f32.bf16.bf16.f32 "
                 "{%0,%1,%2,%3}, {%4,%5,%6,%7}, {%8,%9}, {%0,%1,%2,%3};"
                 : "+f"(c[0]), "+f"(c[1]), "+f"(c[2]), "+f"(c[3])
                 : "r"(a[0]), "r"(a[1]), "r"(a[2]), "r"(a[3]), "r"(b[0]), "r"(b[1]));
}
#define SWZ(off) ((off) ^ (((off) >> 3) & 0x70))

// ---------------------------------------------------------------- converters
__device__ __forceinline__ uint32_t pack_bf2(__nv_bfloat16 lo, __nv_bfloat16 hi) {
    return (uint32_t)__bfloat16_as_ushort(lo) | ((uint32_t)__bfloat16_as_ushort(hi) << 16);
}

__global__ void convertW_kernel(const float* __restrict__ W) {
    size_t i = ((size_t)blockIdx.x * 256 + threadIdx.x) * 4;
    int row = (int)(i >> 10);
    int col = (int)(i & 1023);
    float4 w = *(const float4*)(W + i);
    __nv_bfloat16 h0 = __float2bfloat16_rn(w.x), h1 = __float2bfloat16_rn(w.y);
    __nv_bfloat16 h2 = __float2bfloat16_rn(w.z), h3 = __float2bfloat16_rn(w.w);
    __nv_bfloat16 l0 = __float2bfloat16_rn(w.x - __bfloat162float(h0));
    __nv_bfloat16 l1 = __float2bfloat16_rn(w.y - __bfloat162float(h1));
    __nv_bfloat16 l2 = __float2bfloat16_rn(w.z - __bfloat162float(h2));
    __nv_bfloat16 l3 = __float2bfloat16_rn(w.w - __bfloat162float(h3));
    uint2 hi = make_uint2(pack_bf2(h0, h1), pack_bf2(h2, h3));
    uint2 lo = make_uint2(pack_bf2(l0, l1), pack_bf2(l2, l3));
    char* base = (char*)g_B2 + ((size_t)row * KP) * 2;
    *(uint2*)(base + (size_t)(col) * 2)        = hi;  // Bh
    *(uint2*)(base + (size_t)(1024 + col) * 2) = lo;  // Bl
    *(uint2*)(base + (size_t)(2048 + col) * 2) = hi;  // Bh
}

__global__ void convertA_kernel(const float* __restrict__ A) {
    size_t i = ((size_t)blockIdx.x * 256 + threadIdx.x) * 4;
    int row = (int)(i >> 10);
    int col = (int)(i & 1023);
    float4 w = *(const float4*)(A + i);
    __nv_bfloat16 h0 = __float2bfloat16_rn(w.x), h1 = __float2bfloat16_rn(w.y);
    __nv_bfloat16 h2 = __float2bfloat16_rn(w.z), h3 = __float2bfloat16_rn(w.w);
    __nv_bfloat16 l0 = __float2bfloat16_rn(w.x - __bfloat162float(h0));
    __nv_bfloat16 l1 = __float2bfloat16_rn(w.y - __bfloat162float(h1));
    __nv_bfloat16 l2 = __float2bfloat16_rn(w.z - __bfloat162float(h2));
    __nv_bfloat16 l3 = __float2bfloat16_rn(w.w - __bfloat162float(h3));
    uint2 hi = make_uint2(pack_bf2(h0, h1), pack_bf2(h2, h3));
    uint2 lo = make_uint2(pack_bf2(l0, l1), pack_bf2(l2, l3));
    char* base = (char*)g_A2 + ((size_t)row * KP) * 2;
    *(uint2*)(base + (size_t)(col) * 2)        = hi;  // Ah
    *(uint2*)(base + (size_t)(1024 + col) * 2) = hi;  // Ah
    *(uint2*)(base + (size_t)(2048 + col) * 2) = lo;  // Al
}

// ---------------------------------------------------------------- emb kernel
__global__ void emb_kernel(const int* __restrict__ ids,
                           const float* __restrict__ weight,
                           const float* __restrict__ weight_bit,
                           float* __restrict__ id_emb,
                           float* __restrict__ bit_emb) {
    int bs = blockIdx.x;
    int id = ids[bs];
    id = min(max(id, 0), N_VOCAB - 1);
    int d = threadIdx.x * 4;

    float4 w = *(const float4*)(weight + (size_t)id * K_DIM + d);
    *(float4*)(id_emb + (size_t)bs * K_DIM + d) = w;

    float4 acc = make_float4(0.f, 0.f, 0.f, 0.f);
#pragma unroll
    for (int k = 0; k < NBITS; k++) {
        float s = ((id >> (NBITS - 1 - k)) & 1) ? 1.0f : -1.0f;
        float4 wb = *(const float4*)(weight_bit + k * K_DIM + d);
        acc.x += s * wb.x; acc.y += s * wb.y; acc.z += s * wb.z; acc.w += s * wb.w;
    }
    *(float4*)(bit_emb + (size_t)bs * K_DIM + d) = acc;
}

// ---------------------------------------------------------------- GEMM (mma.sync, 64x64 warp tiles)
__device__ __forceinline__ void load_stage(uint32_t sA, int m0, int n0, int kb, int tid) {
    uint32_t sB = sA + 16384;
#pragma unroll
    for (int u = 0; u < 4; ++u) {           // A: 1024 16B segs
        int seg = tid + u * 256;
        int row = seg >> 3, c = seg & 7;
        uint32_t off = row * 128 + c * 16;
        cp_async16(sA + SWZ(off),
                   (const char*)g_A2 + ((size_t)(m0 + row) * KP + kb * 64 + c * 8) * 2);
    }
#pragma unroll
    for (int u = 0; u < 8; ++u) {           // B: 2048 16B segs
        int seg = tid + u * 256;
        int row = seg >> 3, c = seg & 7;
        uint32_t off = row * 128 + c * 16;
        cp_async16(sB + SWZ(off),
                   (const char*)g_B2 + ((size_t)(n0 + row) * KP + kb * 64 + c * 8) * 2);
    }
}

__global__ void __launch_bounds__(256, 1)
gemm_mma_kernel(float* __restrict__ logit) {
    extern __shared__ char dynsmem[];
    const int tid = threadIdx.x;
    const int lane = tid & 31;
    const int wid = tid >> 5;
    const int warp_m = wid >> 2;        // 0..1 (64 rows)
    const int warp_n = wid & 3;         // 0..3 (64 cols)
    const int m0 = blockIdx.x * BM;     // m fastest -> B reuse in L2
    const int n0 = blockIdx.y * BN;

    uint32_t tile0 = (smem_u32(dynsmem) + 127) & ~127u;

    // ldmatrix per-lane addressing
    const int a_row   = warp_m * 64 + (lane & 15);
    const int a_chunk = lane >> 4;                          // 0/1 -> k8 half
    const int bg      = lane >> 3;                          // 0..3
    const int b_row   = warp_n * 64 + ((bg >> 1) << 3) + (lane & 7);
    const int b_chunk = bg & 1;

    float acc[4][8][4];
#pragma unroll
    for (int i = 0; i < 4; i++)
#pragma unroll
        for (int j = 0; j < 8; j++)
#pragma unroll
            for (int q = 0; q < 4; q++) acc[i][j][q] = 0.f;

    // prologue: stages 0..2
    load_stage(tile0 + 0 * STAGE, m0, n0, 0, tid); cp_commit();
    load_stage(tile0 + 1 * STAGE, m0, n0, 1, tid); cp_commit();
    load_stage(tile0 + 2 * STAGE, m0, n0, 2, tid); cp_commit();

#pragma unroll 1
    for (int kt = 0; kt < NKI; ++kt) {
        cp_wait<2>();
        __syncthreads();

        int kn = kt + 3;
        if (kn < NKI) load_stage(tile0 + (kn & 3) * STAGE, m0, n0, kn, tid);
        cp_commit();

        uint32_t sA = tile0 + (kt & 3) * STAGE;
        uint32_t sB = sA + 16384;

#pragma unroll
        for (int ks = 0; ks < 4; ++ks) {
            uint32_t af[4][4];
            uint32_t bf[4][4];
#pragma unroll
            for (int i = 0; i < 4; ++i) {
                uint32_t off = (uint32_t)(a_row + i * 16) * 128 + (ks * 2 + a_chunk) * 16;
                ldsm_x4(af[i], sA + SWZ(off));
            }
#pragma unroll
            for (int jj = 0; jj < 4; ++jj) {
                uint32_t off = (uint32_t)(b_row + jj * 16) * 128 + (ks * 2 + b_chunk) * 16;
                ldsm_x4(bf[jj], sB + SWZ(off));
            }
#pragma unroll
            for (int i = 0; i < 4; ++i)
#pragma unroll
                for (int j = 0; j < 8; ++j)
                    mma_bf16(acc[i][j], af[i], &bf[j >> 1][(j & 1) * 2]);
        }
    }

    // ---------------- epilogue: store logits + fused softmax partials (64-wide tiles)
    const int n_base = n0 + warp_n * 64;
    const int t64 = n_base >> 6;

#pragma unroll
    for (int i = 0; i < 4; ++i) {
#pragma unroll
        for (int half = 0; half < 2; ++half) {
            const int gm = m0 + warp_m * 64 + i * 16 + (lane >> 2) + half * 8;
            float v[16];
#pragma unroll
            for (int j = 0; j < 8; ++j) {
                v[2 * j]     = acc[i][j][half * 2];
                v[2 * j + 1] = acc[i][j][half * 2 + 1];
            }
            float* p = logit + (size_t)gm * N_VOCAB + n_base;
#pragma unroll
            for (int j = 0; j < 8; ++j)
                *(float2*)(p + j * 8 + (lane & 3) * 2) = make_float2(v[2 * j], v[2 * j + 1]);

            float mx = v[0];
#pragma unroll
            for (int q = 1; q < 16; ++q) mx = fmaxf(mx, v[q]);
            mx = fmaxf(mx, __shfl_xor_sync(0xffffffffu, mx, 1));
            mx = fmaxf(mx, __shfl_xor_sync(0xffffffffu, mx, 2));

            float S = 0.f, b0 = 0.f, b3 = 0.f, b4 = 0.f, b5 = 0.f;
#pragma unroll
            for (int j = 0; j < 8; ++j) {
                float e0 = __expf(v[2 * j] - mx);
                float e1 = __expf(v[2 * j + 1] - mx);
                float s2 = e0 + e1;
                S += s2;
                b0 += e1;                    // col bit0 = odd element
                if (j & 1) b3 += s2;         // col bit3 = j&1
                if (j & 2) b4 += s2;         // col bit4 = j&2
                if (j & 4) b5 += s2;         // col bit5 = j&4
            }
            float b1 = (lane & 1) ? S : 0.f;     // col bit1
            float b2 = (lane & 2) ? S : 0.f;     // col bit2

#pragma unroll
            for (int o = 1; o <= 2; o <<= 1) {
                S  += __shfl_xor_sync(0xffffffffu, S, o);
                b0 += __shfl_xor_sync(0xffffffffu, b0, o);
                b1 += __shfl_xor_sync(0xffffffffu, b1, o);
                b2 += __shfl_xor_sync(0xffffffffu, b2, o);
                b3 += __shfl_xor_sync(0xffffffffu, b3, o);
                b4 += __shfl_xor_sync(0xffffffffu, b4, o);
                b5 += __shfl_xor_sync(0xffffffffu, b5, o);
            }

            if ((lane & 3) == 0) {
                int idx = gm * NT64 + t64;
                g_pmax[idx] = mx;
                g_psum[idx] = S;
                float* pn = g_pnum + (size_t)idx * 6;
                pn[0] = b5;   // logit_w k=9  (bit 5)
                pn[1] = b4;   // k=10
                pn[2] = b3;   // k=11
                pn[3] = b2;   // k=12
                pn[4] = b1;   // k=13
                pn[5] = b0;   // k=14 (bit 0)
            }
        }
    }
}

// ---------------------------------------------------------------- reduce
__global__ void reduce_kernel(float* __restrict__ logit_w) {
    int row = blockIdx.x;
    int lane = threadIdx.x;

    float lmax = -3.402823466e38f;
    for (int t = lane; t < NT64; t += 32)
        lmax = fmaxf(lmax, g_pmax[row * NT64 + t]);
#pragma unroll
    for (int o = 16; o >= 1; o >>= 1)
        lmax = fmaxf(lmax, __shfl_xor_sync(0xffffffffu, lmax, o));

    float tot = 0.f;
    float num[NBITS];
#pragma unroll
    for (int k = 0; k < NBITS; k++) num[k] = 0.f;

    for (int t = lane; t < NT64; t += 32) {
        int idx = row * NT64 + t;
        float w = __expf(g_pmax[idx] - lmax);
        float Sw = g_psum[idx] * w;
        tot += Sw;
        int vb = t << 6;                       // tile vocab base (high 9 bits constant)
#pragma unroll
        for (int k = 0; k < 9; k++)
            if ((vb >> (14 - k)) & 1) num[k] += Sw;
        const float* pn = g_pnum + (size_t)idx * 6;
        num[9]  += pn[0] * w;
        num[10] += pn[1] * w;
        num[11] += pn[2] * w;
        num[12] += pn[3] * w;
        num[13] += pn[4] * w;
        num[14] += pn[5] * w;
    }
#pragma unroll
    for (int o = 16; o >= 1; o >>= 1) {
        tot += __shfl_xor_sync(0xffffffffu, tot, o);
#pragma unroll
        for (int k = 0; k < NBITS; k++)
            num[k] += __shfl_xor_sync(0xffffffffu, num[k], o);
    }

    if (lane == 0) {
#pragma unroll
        for (int k = 0; k < NBITS; k++)
            logit_w[row * NBITS + k] = (2.f * num[k] - tot) / tot;
    }
}

// ---------------------------------------------------------------- launch
extern "C" void kernel_launch(void* const* d_in, const int* in_sizes, int n_in,
                              void* d_out, int out_size) {
    const int*   ids        = (const int*)d_in[0];
    const float* tensor     = (const float*)d_in[1];
    const float* weight     = (const float*)d_in[2];
    const float* weight_bit = (const float*)d_in[3];

    float* out     = (float*)d_out;
    float* id_emb  = out;
    float* bit_emb = out + 4194304;
    float* logit   = out + 8388608;
    float* logit_w = out + 8388608 + 131072000;

    cudaFuncSetAttribute(gemm_mma_kernel, cudaFuncAttributeMaxDynamicSharedMemorySize, DSMEM);

    convertA_kernel<<<4096, 256>>>(tensor);
    convertW_kernel<<<32000, 256>>>(weight);
    emb_kernel<<<M_TOTAL, 256>>>(ids, weight, weight_bit, id_emb, bit_emb);
    gemm_mma_kernel<<<dim3(M_TOTAL / BM, N_VOCAB / BN), 256, DSMEM>>>(logit);
    reduce_kernel<<<M_TOTAL, 32>>>(logit_w);
}

// round 14
// speedup vs baseline: 6.4119x; 1.0860x over previous
#include <cuda_runtime.h>
#include <cuda_bf16.h>
#include <math.h>
#include <stdint.h>

// ---------------------------------------------------------------- shapes
#define M_TOTAL 4096
#define K_DIM   1024
#define N_VOCAB 32000
#define NBITS   15
#define KP2     2048            // stored cols: [hi | lo]
#define BM      128
#define BN      128
#define NKI     48              // virtual K' = 3072 over BK=64
#define NT2     1000            // 32-wide partial tiles per row

#define STAGE   32768           // 16KB A + 16KB B
#define NSTAGE  3
#define DSMEM   (NSTAGE * STAGE + 128)

// ---------------------------------------------------------------- scratch
__device__ __nv_bfloat16 g_A2[(size_t)M_TOTAL * KP2];   // [Ah | Al]
__device__ __nv_bfloat16 g_B2[(size_t)N_VOCAB * KP2];   // [Bh | Bl]
__device__ float g_pmax[M_TOTAL * NT2];
__device__ float g_psum[M_TOTAL * NT2];
__device__ float g_pnum[(size_t)M_TOTAL * NT2 * 5];

// ---------------------------------------------------------------- helpers
__device__ __forceinline__ uint32_t smem_u32(const void* p) {
    uint32_t a;
    asm("{ .reg .u64 t; cvta.to.shared.u64 t, %1; cvt.u32.u64 %0, t; }" : "=r"(a) : "l"(p));
    return a;
}
__device__ __forceinline__ void cp_async16(uint32_t dst, const void* src) {
    asm volatile("cp.async.cg.shared.global [%0], [%1], 16;" :: "r"(dst), "l"(src) : "memory");
}
__device__ __forceinline__ void cp_commit() {
    asm volatile("cp.async.commit_group;" ::: "memory");
}
template <int N>
__device__ __forceinline__ void cp_wait() {
    asm volatile("cp.async.wait_group %0;" :: "n"(N) : "memory");
}
__device__ __forceinline__ void ldsm_x4(uint32_t* r, uint32_t addr) {
    asm volatile("ldmatrix.sync.aligned.m8n8.x4.shared.b16 {%0,%1,%2,%3}, [%4];"
                 : "=r"(r[0]), "=r"(r[1]), "=r"(r[2]), "=r"(r[3]) : "r"(addr));
}
__device__ __forceinline__ void mma_bf16(float* c, const uint32_t* a, const uint32_t* b) {
    asm volatile("mma.sync.aligned.m16n8k16.row.col.f32.bf16.bf16.f32 "
                 "{%0,%1,%2,%3}, {%4,%5,%6,%7}, {%8,%9}, {%0,%1,%2,%3};"
                 : "+f"(c[0]), "+f"(c[1]), "+f"(c[2]), "+f"(c[3])
                 : "r"(a[0]), "r"(a[1]), "r"(a[2]), "r"(a[3]), "r"(b[0]), "r"(b[1]));
}
#define SWZ(off) ((off) ^ (((off) >> 3) & 0x70))

// ---------------------------------------------------------------- fused prep
__device__ __forceinline__ uint32_t pack_bf2(__nv_bfloat16 lo, __nv_bfloat16 hi) {
    return (uint32_t)__bfloat16_as_ushort(lo) | ((uint32_t)__bfloat16_as_ushort(hi) << 16);
}

__global__ void prep_kernel(const float* __restrict__ tensor,
                            const float* __restrict__ weight,
                            const float* __restrict__ weight_bit,
                            const int* __restrict__ ids,
                            float* __restrict__ id_emb,
                            float* __restrict__ bit_emb) {
    int b = blockIdx.x;
    if (b < 36096) {
        const float* src = (b < 4096) ? tensor : weight;
        __nv_bfloat16* dst = (b < 4096) ? g_A2 : g_B2;
        int row = (b < 4096) ? b : (b - 4096);
        int col = threadIdx.x * 4;
        float4 w = *(const float4*)(src + (size_t)row * K_DIM + col);
        __nv_bfloat16 h0 = __float2bfloat16_rn(w.x), h1 = __float2bfloat16_rn(w.y);
        __nv_bfloat16 h2 = __float2bfloat16_rn(w.z), h3 = __float2bfloat16_rn(w.w);
        __nv_bfloat16 l0 = __float2bfloat16_rn(w.x - __bfloat162float(h0));
        __nv_bfloat16 l1 = __float2bfloat16_rn(w.y - __bfloat162float(h1));
        __nv_bfloat16 l2 = __float2bfloat16_rn(w.z - __bfloat162float(h2));
        __nv_bfloat16 l3 = __float2bfloat16_rn(w.w - __bfloat162float(h3));
        char* base = (char*)dst + (size_t)row * KP2 * 2;
        *(uint2*)(base + (size_t)col * 2) =
            make_uint2(pack_bf2(h0, h1), pack_bf2(h2, h3));
        *(uint2*)(base + (size_t)(1024 + col) * 2) =
            make_uint2(pack_bf2(l0, l1), pack_bf2(l2, l3));
    } else {
        int bs = b - 36096;
        int id = ids[bs];
        id = min(max(id, 0), N_VOCAB - 1);
        int d = threadIdx.x * 4;
        float4 w = *(const float4*)(weight + (size_t)id * K_DIM + d);
        *(float4*)(id_emb + (size_t)bs * K_DIM + d) = w;
        float4 acc = make_float4(0.f, 0.f, 0.f, 0.f);
#pragma unroll
        for (int k = 0; k < NBITS; k++) {
            float s = ((id >> (NBITS - 1 - k)) & 1) ? 1.0f : -1.0f;
            float4 wb = *(const float4*)(weight_bit + k * K_DIM + d);
            acc.x += s * wb.x; acc.y += s * wb.y; acc.z += s * wb.z; acc.w += s * wb.w;
        }
        *(float4*)(bit_emb + (size_t)bs * K_DIM + d) = acc;
    }
}

// ---------------------------------------------------------------- GEMM (mma.sync)
// virtual K' = 3072: terms A:[Ah|Ah|Al] x B:[Bh|Bl|Bh], remapped into compact
// [hi|lo] storage: kbA = kb<16?kb:kb-16 ; kbB = kb<32?kb:kb-32
__device__ __forceinline__ void load_stage(uint32_t sA, int m0, int n0, int kb, int tid) {
    uint32_t sB = sA + 16384;
    const int kbA = (kb < 16) ? kb : kb - 16;
    const int kbB = (kb < 32) ? kb : kb - 32;
#pragma unroll
    for (int u = 0; u < 4; ++u) {
        int seg = tid + u * 256;
        int row = seg >> 3, c = seg & 7;
        uint32_t off = row * 128 + c * 16;
        cp_async16(sA + SWZ(off),
                   (const char*)g_A2 + ((size_t)(m0 + row) * KP2 + kbA * 64 + c * 8) * 2);
    }
#pragma unroll
    for (int u = 0; u < 4; ++u) {
        int seg = tid + u * 256;
        int row = seg >> 3, c = seg & 7;
        uint32_t off = row * 128 + c * 16;
        cp_async16(sB + SWZ(off),
                   (const char*)g_B2 + ((size_t)(n0 + row) * KP2 + kbB * 64 + c * 8) * 2);
    }
}

__global__ void __launch_bounds__(256, 2)
gemm_mma_kernel(float* __restrict__ logit) {
    extern __shared__ char dynsmem[];
    const int tid = threadIdx.x;
    const int lane = tid & 31;
    const int wid = tid >> 5;
    const int warp_m = wid >> 2;        // 0..1 (64 rows)
    const int warp_n = wid & 3;         // 0..3 (32 cols)
    const int m0 = blockIdx.x * BM;     // m fastest -> B reuse in L2
    const int n0 = blockIdx.y * BN;

    uint32_t tile0 = (smem_u32(dynsmem) + 127) & ~127u;

    const int a_row   = warp_m * 64 + (lane & 15);
    const int a_chunk = lane >> 4;
    const int bg      = lane >> 3;
    const int b_row   = warp_n * 32 + ((bg >> 1) << 3) + (lane & 7);
    const int b_chunk = bg & 1;

    float acc[4][4][4];
#pragma unroll
    for (int i = 0; i < 4; i++)
#pragma unroll
        for (int j = 0; j < 4; j++)
#pragma unroll
            for (int q = 0; q < 4; q++) acc[i][j][q] = 0.f;

    load_stage(tile0 + 0 * STAGE, m0, n0, 0, tid); cp_commit();
    load_stage(tile0 + 1 * STAGE, m0, n0, 1, tid); cp_commit();

#pragma unroll 1
    for (int kt = 0; kt < NKI; ++kt) {
        cp_wait<1>();                 // my stage-kt copies done
        __syncthreads();              // everyone's done copies visible; stage (kt+2)%3 free

        int kn = kt + 2;
        if (kn < NKI) load_stage(tile0 + (kn % NSTAGE) * STAGE, m0, n0, kn, tid);
        cp_commit();

        uint32_t sA = tile0 + (kt % NSTAGE) * STAGE;
        uint32_t sB = sA + 16384;

#pragma unroll
        for (int ks = 0; ks < 4; ++ks) {
            uint32_t af[4][4];
            uint32_t bf[2][4];
#pragma unroll
            for (int i = 0; i < 4; ++i) {
                uint32_t off = (uint32_t)(a_row + i * 16) * 128 + (ks * 2 + a_chunk) * 16;
                ldsm_x4(af[i], sA + SWZ(off));
            }
#pragma unroll
            for (int j = 0; j < 2; ++j) {
                uint32_t off = (uint32_t)(b_row + j * 16) * 128 + (ks * 2 + b_chunk) * 16;
                ldsm_x4(bf[j], sB + SWZ(off));
            }
#pragma unroll
            for (int i = 0; i < 4; ++i)
#pragma unroll
                for (int jj = 0; jj < 4; ++jj)
                    mma_bf16(acc[i][jj], af[i], &bf[jj >> 1][(jj & 1) * 2]);
        }
    }

    // ---------------- epilogue: store logits + fused softmax partials
    const int n_base = n0 + warp_n * 32;
    const int t32 = n_base >> 5;

#pragma unroll
    for (int i = 0; i < 4; ++i) {
#pragma unroll
        for (int half = 0; half < 2; ++half) {
            const int gm = m0 + warp_m * 64 + i * 16 + (lane >> 2) + half * 8;
            float v[8];
#pragma unroll
            for (int j = 0; j < 4; ++j) {
                v[2 * j]     = acc[i][j][half * 2];
                v[2 * j + 1] = acc[i][j][half * 2 + 1];
            }
            float* p = logit + (size_t)gm * N_VOCAB + n_base;
#pragma unroll
            for (int j = 0; j < 4; ++j)
                *(float2*)(p + j * 8 + (lane & 3) * 2) = make_float2(v[2 * j], v[2 * j + 1]);

            float mx = v[0];
#pragma unroll
            for (int q = 1; q < 8; ++q) mx = fmaxf(mx, v[q]);
            mx = fmaxf(mx, __shfl_xor_sync(0xffffffffu, mx, 1));
            mx = fmaxf(mx, __shfl_xor_sync(0xffffffffu, mx, 2));

            float S = 0.f, b0 = 0.f, b3 = 0.f, b4 = 0.f;
#pragma unroll
            for (int j = 0; j < 4; ++j) {
                float e0 = __expf(v[2 * j] - mx);
                float e1 = __expf(v[2 * j + 1] - mx);
                float s2 = e0 + e1;
                S += s2;
                b0 += e1;
                if (j & 1) b3 += s2;
                if (j & 2) b4 += s2;
            }
            float b1 = (lane & 1) ? S : 0.f;
            float b2 = (lane & 2) ? S : 0.f;

#pragma unroll
            for (int o = 1; o <= 2; o <<= 1) {
                S  += __shfl_xor_sync(0xffffffffu, S, o);
                b0 += __shfl_xor_sync(0xffffffffu, b0, o);
                b1 += __shfl_xor_sync(0xffffffffu, b1, o);
                b2 += __shfl_xor_sync(0xffffffffu, b2, o);
                b3 += __shfl_xor_sync(0xffffffffu, b3, o);
                b4 += __shfl_xor_sync(0xffffffffu, b4, o);
            }

            if ((lane & 3) == 0) {
                int idx = gm * NT2 + t32;
                g_pmax[idx] = mx;
                g_psum[idx] = S;
                float* pn = g_pnum + (size_t)idx * 5;
                pn[0] = b4; pn[1] = b3; pn[2] = b2; pn[3] = b1; pn[4] = b0;
            }
        }
    }
}

// ---------------------------------------------------------------- reduce
__global__ void reduce_kernel(float* __restrict__ logit_w) {
    int row = blockIdx.x;
    int lane = threadIdx.x;

    float lmax = -3.402823466e38f;
    for (int t = lane; t < NT2; t += 32)
        lmax = fmaxf(lmax, g_pmax[row * NT2 + t]);
#pragma unroll
    for (int o = 16; o >= 1; o >>= 1)
        lmax = fmaxf(lmax, __shfl_xor_sync(0xffffffffu, lmax, o));

    float tot = 0.f;
    float num[NBITS];
#pragma unroll
    for (int k = 0; k < NBITS; k++) num[k] = 0.f;

    for (int t = lane; t < NT2; t += 32) {
        int idx = row * NT2 + t;
        float w = __expf(g_pmax[idx] - lmax);
        float Sw = g_psum[idx] * w;
        tot += Sw;
        int vb = t << 5;
#pragma unroll
        for (int k = 0; k < 10; k++)
            if ((vb >> (14 - k)) & 1) num[k] += Sw;
        const float* pn = g_pnum + (size_t)idx * 5;
        num[10] += pn[0] * w;
        num[11] += pn[1] * w;
        num[12] += pn[2] * w;
        num[13] += pn[3] * w;
        num[14] += pn[4] * w;
    }
#pragma unroll
    for (int o = 16; o >= 1; o >>= 1) {
        tot += __shfl_xor_sync(0xffffffffu, tot, o);
#pragma unroll
        for (int k = 0; k < NBITS; k++)
            num[k] += __shfl_xor_sync(0xffffffffu, num[k], o);
    }

    if (lane == 0) {
#pragma unroll
        for (int k = 0; k < NBITS; k++)
            logit_w[row * NBITS + k] = (2.f * num[k] - tot) / tot;
    }
}

// ---------------------------------------------------------------- launch
extern "C" void kernel_launch(void* const* d_in, const int* in_sizes, int n_in,
                              void* d_out, int out_size) {
    const int*   ids        = (const int*)d_in[0];
    const float* tensor     = (const float*)d_in[1];
    const float* weight     = (const float*)d_in[2];
    const float* weight_bit = (const float*)d_in[3];

    float* out     = (float*)d_out;
    float* id_emb  = out;
    float* bit_emb = out + 4194304;
    float* logit   = out + 8388608;
    float* logit_w = out + 8388608 + 131072000;

    cudaFuncSetAttribute(gemm_mma_kernel, cudaFuncAttributeMaxDynamicSharedMemorySize, DSMEM);

    prep_kernel<<<40192, 256>>>(tensor, weight, weight_bit, ids, id_emb, bit_emb);
    gemm_mma_kernel<<<dim3(M_TOTAL / BM, N_VOCAB / BN), 256, DSMEM>>>(logit);
    reduce_kernel<<<M_TOTAL, 32>>>(logit_w);
}

// round 15
// speedup vs baseline: 6.6614x; 1.0389x over previous
#include <cuda_runtime.h>
#include <cuda_bf16.h>
#include <math.h>
#include <stdint.h>

// ---------------------------------------------------------------- shapes
#define M_TOTAL 4096
#define K_DIM   1024
#define N_VOCAB 32000
#define NBITS   15
#define KP2     2048            // stored cols: [hi | lo]
#define BM      128
#define BN      128
#define NKI     48              // virtual K' = 3072 over BK=64
#define NT64    500             // 64-wide partial tiles per row
#define NTHR    128             // 4 warps: 2x2 of 64x64 tiles

#define STAGE   32768           // 16KB A + 16KB B
#define NSTAGE  3
#define DSMEM   (NSTAGE * STAGE + 128)

// ---------------------------------------------------------------- scratch
__device__ __nv_bfloat16 g_A2[(size_t)M_TOTAL * KP2];   // [Ah | Al]
__device__ __nv_bfloat16 g_B2[(size_t)N_VOCAB * KP2];   // [Bh | Bl]
__device__ float g_pmax[M_TOTAL * NT64];
__device__ float g_psum[M_TOTAL * NT64];
__device__ float g_pnum[(size_t)M_TOTAL * NT64 * 6];

// ---------------------------------------------------------------- helpers
__device__ __forceinline__ uint32_t smem_u32(const void* p) {
    uint32_t a;
    asm("{ .reg .u64 t; cvta.to.shared.u64 t, %1; cvt.u32.u64 %0, t; }" : "=r"(a) : "l"(p));
    return a;
}
__device__ __forceinline__ void cp_async16(uint32_t dst, const void* src) {
    asm volatile("cp.async.cg.shared.global [%0], [%1], 16;" :: "r"(dst), "l"(src) : "memory");
}
__device__ __forceinline__ void cp_commit() {
    asm volatile("cp.async.commit_group;" ::: "memory");
}
template <int N>
__device__ __forceinline__ void cp_wait() {
    asm volatile("cp.async.wait_group %0;" :: "n"(N) : "memory");
}
__device__ __forceinline__ void ldsm_x4(uint32_t* r, uint32_t addr) {
    asm volatile("ldmatrix.sync.aligned.m8n8.x4.shared.b16 {%0,%1,%2,%3}, [%4];"
                 : "=r"(r[0]), "=r"(r[1]), "=r"(r[2]), "=r"(r[3]) : "r"(addr));
}
__device__ __forceinline__ void mma_bf16(float* c, const uint32_t* a, const uint32_t* b) {
    asm volatile("mma.sync.aligned.m16n8k16.row.col.f32.bf16.bf16.f32 "
                 "{%0,%1,%2,%3}, {%4,%5,%6,%7}, {%8,%9}, {%0,%1,%2,%3};"
                 : "+f"(c[0]), "+f"(c[1]), "+f"(c[2]), "+f"(c[3])
                 : "r"(a[0]), "r"(a[1]), "r"(a[2]), "r"(a[3]), "r"(b[0]), "r"(b[1]));
}
#define SWZ(off) ((off) ^ (((off) >> 3) & 0x70))

// ---------------------------------------------------------------- fused prep
__device__ __forceinline__ uint32_t pack_bf2(__nv_bfloat16 lo, __nv_bfloat16 hi) {
    return (uint32_t)__bfloat16_as_ushort(lo) | ((uint32_t)__bfloat16_as_ushort(hi) << 16);
}

__global__ void prep_kernel(const float* __restrict__ tensor,
                            const float* __restrict__ weight,
                            const float* __restrict__ weight_bit,
                            const int* __restrict__ ids,
                            float* __restrict__ id_emb,
                            float* __restrict__ bit_emb) {
    int b = blockIdx.x;
    if (b < 36096) {
        const float* src = (b < 4096) ? tensor : weight;
        __nv_bfloat16* dst = (b < 4096) ? g_A2 : g_B2;
        int row = (b < 4096) ? b : (b - 4096);
        int col = threadIdx.x * 4;
        float4 w = *(const float4*)(src + (size_t)row * K_DIM + col);
        __nv_bfloat16 h0 = __float2bfloat16_rn(w.x), h1 = __float2bfloat16_rn(w.y);
        __nv_bfloat16 h2 = __float2bfloat16_rn(w.z), h3 = __float2bfloat16_rn(w.w);
        __nv_bfloat16 l0 = __float2bfloat16_rn(w.x - __bfloat162float(h0));
        __nv_bfloat16 l1 = __float2bfloat16_rn(w.y - __bfloat162float(h1));
        __nv_bfloat16 l2 = __float2bfloat16_rn(w.z - __bfloat162float(h2));
        __nv_bfloat16 l3 = __float2bfloat16_rn(w.w - __bfloat162float(h3));
        char* base = (char*)dst + (size_t)row * KP2 * 2;
        *(uint2*)(base + (size_t)col * 2) =
            make_uint2(pack_bf2(h0, h1), pack_bf2(h2, h3));
        *(uint2*)(base + (size_t)(1024 + col) * 2) =
            make_uint2(pack_bf2(l0, l1), pack_bf2(l2, l3));
    } else {
        int bs = b - 36096;
        int id = ids[bs];
        id = min(max(id, 0), N_VOCAB - 1);
        int d = threadIdx.x * 4;
        float4 w = *(const float4*)(weight + (size_t)id * K_DIM + d);
        *(float4*)(id_emb + (size_t)bs * K_DIM + d) = w;
        float4 acc = make_float4(0.f, 0.f, 0.f, 0.f);
#pragma unroll
        for (int k = 0; k < NBITS; k++) {
            float s = ((id >> (NBITS - 1 - k)) & 1) ? 1.0f : -1.0f;
            float4 wb = *(const float4*)(weight_bit + k * K_DIM + d);
            acc.x += s * wb.x; acc.y += s * wb.y; acc.z += s * wb.z; acc.w += s * wb.w;
        }
        *(float4*)(bit_emb + (size_t)bs * K_DIM + d) = acc;
    }
}

// ---------------------------------------------------------------- GEMM (mma.sync, 2x2 warps of 64x64)
// virtual K' = 3072: terms A:[Ah|Ah|Al] x B:[Bh|Bl|Bh]; compact storage remap:
// kbA = kb<16?kb:kb-16 ; kbB = kb<32?kb:kb-32
__device__ __forceinline__ void load_stage(uint32_t sA, int m0, int n0, int kb, int tid) {
    uint32_t sB = sA + 16384;
    const int kbA = (kb < 16) ? kb : kb - 16;
    const int kbB = (kb < 32) ? kb : kb - 32;
#pragma unroll
    for (int u = 0; u < 8; ++u) {          // A: 1024 16B segs / 128 thr
        int seg = tid + u * NTHR;
        int row = seg >> 3, c = seg & 7;
        uint32_t off = row * 128 + c * 16;
        cp_async16(sA + SWZ(off),
                   (const char*)g_A2 + ((size_t)(m0 + row) * KP2 + kbA * 64 + c * 8) * 2);
    }
#pragma unroll
    for (int u = 0; u < 8; ++u) {          // B: 1024 16B segs
        int seg = tid + u * NTHR;
        int row = seg >> 3, c = seg & 7;
        uint32_t off = row * 128 + c * 16;
        cp_async16(sB + SWZ(off),
                   (const char*)g_B2 + ((size_t)(n0 + row) * KP2 + kbB * 64 + c * 8) * 2);
    }
}

__global__ void __launch_bounds__(NTHR, 2)
gemm_mma_kernel(float* __restrict__ logit) {
    extern __shared__ char dynsmem[];
    const int tid = threadIdx.x;
    const int lane = tid & 31;
    const int wid = tid >> 5;
    const int warp_m = wid >> 1;        // 0..1 (64 rows)
    const int warp_n = wid & 1;         // 0..1 (64 cols)
    const int m0 = blockIdx.x * BM;     // m fastest -> B reuse in L2
    const int n0 = blockIdx.y * BN;

    uint32_t tile0 = (smem_u32(dynsmem) + 127) & ~127u;

    // ldmatrix per-lane addressing
    const int a_row   = warp_m * 64 + (lane & 15);
    const int a_chunk = lane >> 4;                          // 0/1 -> k8 half
    const int bg      = lane >> 3;                          // 0..3
    const int b_row   = warp_n * 64 + ((bg >> 1) << 3) + (lane & 7);
    const int b_chunk = bg & 1;

    float acc[4][8][4];
#pragma unroll
    for (int i = 0; i < 4; i++)
#pragma unroll
        for (int j = 0; j < 8; j++)
#pragma unroll
            for (int q = 0; q < 4; q++) acc[i][j][q] = 0.f;

    load_stage(tile0 + 0 * STAGE, m0, n0, 0, tid); cp_commit();
    load_stage(tile0 + 1 * STAGE, m0, n0, 1, tid); cp_commit();

#pragma unroll 1
    for (int kt = 0; kt < NKI; ++kt) {
        cp_wait<1>();                 // my stage-kt copies done
        __syncthreads();              // all threads' copies visible; stage (kt+2)%3 free

        int kn = kt + 2;
        if (kn < NKI) load_stage(tile0 + (kn % NSTAGE) * STAGE, m0, n0, kn, tid);
        cp_commit();

        uint32_t sA = tile0 + (kt % NSTAGE) * STAGE;
        uint32_t sB = sA + 16384;

#pragma unroll
        for (int ks = 0; ks < 4; ++ks) {
            uint32_t af[4][4];
            uint32_t bf[4][4];
#pragma unroll
            for (int i = 0; i < 4; ++i) {
                uint32_t off = (uint32_t)(a_row + i * 16) * 128 + (ks * 2 + a_chunk) * 16;
                ldsm_x4(af[i], sA + SWZ(off));
            }
#pragma unroll
            for (int jj = 0; jj < 4; ++jj) {
                uint32_t off = (uint32_t)(b_row + jj * 16) * 128 + (ks * 2 + b_chunk) * 16;
                ldsm_x4(bf[jj], sB + SWZ(off));
            }
#pragma unroll
            for (int i = 0; i < 4; ++i)
#pragma unroll
                for (int j = 0; j < 8; ++j)
                    mma_bf16(acc[i][j], af[i], &bf[j >> 1][(j & 1) * 2]);
        }
    }

    // ---------------- epilogue: store logits + fused softmax partials (64-wide)
    const int n_base = n0 + warp_n * 64;
    const int t64 = n_base >> 6;

#pragma unroll
    for (int i = 0; i < 4; ++i) {
#pragma unroll
        for (int half = 0; half < 2; ++half) {
            const int gm = m0 + warp_m * 64 + i * 16 + (lane >> 2) + half * 8;
            float v[16];
#pragma unroll
            for (int j = 0; j < 8; ++j) {
                v[2 * j]     = acc[i][j][half * 2];
                v[2 * j + 1] = acc[i][j][half * 2 + 1];
            }
            float* p = logit + (size_t)gm * N_VOCAB + n_base;
#pragma unroll
            for (int j = 0; j < 8; ++j)
                *(float2*)(p + j * 8 + (lane & 3) * 2) = make_float2(v[2 * j], v[2 * j + 1]);

            float mx = v[0];
#pragma unroll
            for (int q = 1; q < 16; ++q) mx = fmaxf(mx, v[q]);
            mx = fmaxf(mx, __shfl_xor_sync(0xffffffffu, mx, 1));
            mx = fmaxf(mx, __shfl_xor_sync(0xffffffffu, mx, 2));

            float S = 0.f, b0 = 0.f, b3 = 0.f, b4 = 0.f, b5 = 0.f;
#pragma unroll
            for (int j = 0; j < 8; ++j) {
                float e0 = __expf(v[2 * j] - mx);
                float e1 = __expf(v[2 * j + 1] - mx);
                float s2 = e0 + e1;
                S += s2;
                b0 += e1;                    // col bit0 = odd element
                if (j & 1) b3 += s2;         // col bit3 = j&1
                if (j & 2) b4 += s2;         // col bit4 = j&2
                if (j & 4) b5 += s2;         // col bit5 = j&4
            }
            float b1 = (lane & 1) ? S : 0.f;     // col bit1
            float b2 = (lane & 2) ? S : 0.f;     // col bit2

#pragma unroll
            for (int o = 1; o <= 2; o <<= 1) {
                S  += __shfl_xor_sync(0xffffffffu, S, o);
                b0 += __shfl_xor_sync(0xffffffffu, b0, o);
                b1 += __shfl_xor_sync(0xffffffffu, b1, o);
                b2 += __shfl_xor_sync(0xffffffffu, b2, o);
                b3 += __shfl_xor_sync(0xffffffffu, b3, o);
                b4 += __shfl_xor_sync(0xffffffffu, b4, o);
                b5 += __shfl_xor_sync(0xffffffffu, b5, o);
            }

            if ((lane & 3) == 0) {
                int idx = gm * NT64 + t64;
                g_pmax[idx] = mx;
                g_psum[idx] = S;
                float* pn = g_pnum + (size_t)idx * 6;
                pn[0] = b5;   // logit_w k=9  (bit 5)
                pn[1] = b4;   // k=10
                pn[2] = b3;   // k=11
                pn[3] = b2;   // k=12
                pn[4] = b1;   // k=13
                pn[5] = b0;   // k=14 (bit 0)
            }
        }
    }
}

// ---------------------------------------------------------------- reduce
__global__ void reduce_kernel(float* __restrict__ logit_w) {
    int row = blockIdx.x;
    int lane = threadIdx.x;

    float lmax = -3.402823466e38f;
    for (int t = lane; t < NT64; t += 32)
        lmax = fmaxf(lmax, g_pmax[row * NT64 + t]);
#pragma unroll
    for (int o = 16; o >= 1; o >>= 1)
        lmax = fmaxf(lmax, __shfl_xor_sync(0xffffffffu, lmax, o));

    float tot = 0.f;
    float num[NBITS];
#pragma unroll
    for (int k = 0; k < NBITS; k++) num[k] = 0.f;

    for (int t = lane; t < NT64; t += 32) {
        int idx = row * NT64 + t;
        float w = __expf(g_pmax[idx] - lmax);
        float Sw = g_psum[idx] * w;
        tot += Sw;
        int vb = t << 6;                       // tile vocab base (high 9 bits constant)
#pragma unroll
        for (int k = 0; k < 9; k++)
            if ((vb >> (14 - k)) & 1) num[k] += Sw;
        const float* pn = g_pnum + (size_t)idx * 6;
        num[9]  += pn[0] * w;
        num[10] += pn[1] * w;
        num[11] += pn[2] * w;
        num[12] += pn[3] * w;
        num[13] += pn[4] * w;
        num[14] += pn[5] * w;
    }
#pragma unroll
    for (int o = 16; o >= 1; o >>= 1) {
        tot += __shfl_xor_sync(0xffffffffu, tot, o);
#pragma unroll
        for (int k = 0; k < NBITS; k++)
            num[k] += __shfl_xor_sync(0xffffffffu, num[k], o);
    }

    if (lane == 0) {
#pragma unroll
        for (int k = 0; k < NBITS; k++)
            logit_w[row * NBITS + k] = (2.f * num[k] - tot) / tot;
    }
}

// ---------------------------------------------------------------- launch
extern "C" void kernel_launch(void* const* d_in, const int* in_sizes, int n_in,
                              void* d_out, int out_size) {
    const int*   ids        = (const int*)d_in[0];
    const float* tensor     = (const float*)d_in[1];
    const float* weight     = (const float*)d_in[2];
    const float* weight_bit = (const float*)d_in[3];

    float* out     = (float*)d_out;
    float* id_emb  = out;
    float* bit_emb = out + 4194304;
    float* logit   = out + 8388608;
    float* logit_w = out + 8388608 + 131072000;

    cudaFuncSetAttribute(gemm_mma_kernel, cudaFuncAttributeMaxDynamicSharedMemorySize, DSMEM);

    prep_kernel<<<40192, 256>>>(tensor, weight, weight_bit, ids, id_emb, bit_emb);
    gemm_mma_kernel<<<dim3(M_TOTAL / BM, N_VOCAB / BN), NTHR, DSMEM>>>(logit);
    reduce_kernel<<<M_TOTAL, 32>>>(logit_w);
}

// round 16
// speedup vs baseline: 6.9223x; 1.0392x over previous
#include <cuda_runtime.h>
#include <cuda_bf16.h>
#include <math.h>
#include <stdint.h>

// ---------------------------------------------------------------- shapes
#define M_TOTAL 4096
#define K_DIM   1024
#define N_VOCAB 32000
#define NBITS   15
#define KP2     2048            // stored cols: [hi | lo]
#define BM      128
#define BN      128
#define NKI     48              // virtual K' = 3072 over BK=64
#define NT64    500             // 64-wide partial tiles per row
#define NTHR    128             // 4 warps: 2x2 of 64x64 tiles

#define STAGE   32768           // 16KB A + 16KB B
#define NSTAGE  3
#define DSMEM   (NSTAGE * STAGE + 128)

// ---------------------------------------------------------------- scratch
__device__ __nv_bfloat16 g_A2[(size_t)M_TOTAL * KP2];   // [Ah | Al]
__device__ __nv_bfloat16 g_B2[(size_t)N_VOCAB * KP2];   // [Bh | Bl]
__device__ float g_pmax[M_TOTAL * NT64];
__device__ float g_psum[M_TOTAL * NT64];
__device__ float g_pnum[(size_t)M_TOTAL * NT64 * 6];

// ---------------------------------------------------------------- helpers
__device__ __forceinline__ uint32_t smem_u32(const void* p) {
    uint32_t a;
    asm("{ .reg .u64 t; cvta.to.shared.u64 t, %1; cvt.u32.u64 %0, t; }" : "=r"(a) : "l"(p));
    return a;
}
__device__ __forceinline__ void cp_async16(uint32_t dst, const void* src) {
    asm volatile("cp.async.cg.shared.global [%0], [%1], 16;" :: "r"(dst), "l"(src) : "memory");
}
__device__ __forceinline__ void cp_commit() {
    asm volatile("cp.async.commit_group;" ::: "memory");
}
template <int N>
__device__ __forceinline__ void cp_wait() {
    asm volatile("cp.async.wait_group %0;" :: "n"(N) : "memory");
}
__device__ __forceinline__ void ldsm_x4(uint32_t* r, uint32_t addr) {
    asm volatile("ldmatrix.sync.aligned.m8n8.x4.shared.b16 {%0,%1,%2,%3}, [%4];"
                 : "=r"(r[0]), "=r"(r[1]), "=r"(r[2]), "=r"(r[3]) : "r"(addr));
}
__device__ __forceinline__ void mma_bf16(float* c, const uint32_t* a, const uint32_t* b) {
    asm volatile("mma.sync.aligned.m16n8k16.row.col.f32.bf16.bf16.f32 "
                 "{%0,%1,%2,%3}, {%4,%5,%6,%7}, {%8,%9}, {%0,%1,%2,%3};"
                 : "+f"(c[0]), "+f"(c[1]), "+f"(c[2]), "+f"(c[3])
                 : "r"(a[0]), "r"(a[1]), "r"(a[2]), "r"(a[3]), "r"(b[0]), "r"(b[1]));
}
#define SWZ(off) ((off) ^ (((off) >> 3) & 0x70))

// ---------------------------------------------------------------- fused prep
__device__ __forceinline__ uint32_t pack_bf2(__nv_bfloat16 lo, __nv_bfloat16 hi) {
    return (uint32_t)__bfloat16_as_ushort(lo) | ((uint32_t)__bfloat16_as_ushort(hi) << 16);
}

__global__ void prep_kernel(const float* __restrict__ tensor,
                            const float* __restrict__ weight,
                            const float* __restrict__ weight_bit,
                            const int* __restrict__ ids,
                            float* __restrict__ id_emb,
                            float* __restrict__ bit_emb) {
    int b = blockIdx.x;
    if (b < 36096) {
        const float* src = (b < 4096) ? tensor : weight;
        __nv_bfloat16* dst = (b < 4096) ? g_A2 : g_B2;
        int row = (b < 4096) ? b : (b - 4096);
        int col = threadIdx.x * 4;
        float4 w = *(const float4*)(src + (size_t)row * K_DIM + col);
        __nv_bfloat16 h0 = __float2bfloat16_rn(w.x), h1 = __float2bfloat16_rn(w.y);
        __nv_bfloat16 h2 = __float2bfloat16_rn(w.z), h3 = __float2bfloat16_rn(w.w);
        __nv_bfloat16 l0 = __float2bfloat16_rn(w.x - __bfloat162float(h0));
        __nv_bfloat16 l1 = __float2bfloat16_rn(w.y - __bfloat162float(h1));
        __nv_bfloat16 l2 = __float2bfloat16_rn(w.z - __bfloat162float(h2));
        __nv_bfloat16 l3 = __float2bfloat16_rn(w.w - __bfloat162float(h3));
        char* base = (char*)dst + (size_t)row * KP2 * 2;
        *(uint2*)(base + (size_t)col * 2) =
            make_uint2(pack_bf2(h0, h1), pack_bf2(h2, h3));
        *(uint2*)(base + (size_t)(1024 + col) * 2) =
            make_uint2(pack_bf2(l0, l1), pack_bf2(l2, l3));
    } else {
        int bs = b - 36096;
        int id = ids[bs];
        id = min(max(id, 0), N_VOCAB - 1);
        int d = threadIdx.x * 4;
        float4 w = *(const float4*)(weight + (size_t)id * K_DIM + d);
        *(float4*)(id_emb + (size_t)bs * K_DIM + d) = w;
        float4 acc = make_float4(0.f, 0.f, 0.f, 0.f);
#pragma unroll
        for (int k = 0; k < NBITS; k++) {
            float s = ((id >> (NBITS - 1 - k)) & 1) ? 1.0f : -1.0f;
            float4 wb = *(const float4*)(weight_bit + k * K_DIM + d);
            acc.x += s * wb.x; acc.y += s * wb.y; acc.z += s * wb.z; acc.w += s * wb.w;
        }
        *(float4*)(bit_emb + (size_t)bs * K_DIM + d) = acc;
    }
}

// ---------------------------------------------------------------- GEMM (mma.sync, 2x2 warps of 64x64)
// virtual K' = 3072: terms A:[Ah|Ah|Al] x B:[Bh|Bl|Bh]; compact storage remap:
// kbA = kb<16?kb:kb-16 ; kbB = kb<32?kb:kb-32
__device__ __forceinline__ void load_stage(uint32_t sA, int m0, int n0, int kb, int tid) {
    uint32_t sB = sA + 16384;
    const int kbA = (kb < 16) ? kb : kb - 16;
    const int kbB = (kb < 32) ? kb : kb - 32;
#pragma unroll
    for (int u = 0; u < 8; ++u) {          // A: 1024 16B segs / 128 thr
        int seg = tid + u * NTHR;
        int row = seg >> 3, c = seg & 7;
        uint32_t off = row * 128 + c * 16;
        cp_async16(sA + SWZ(off),
                   (const char*)g_A2 + ((size_t)(m0 + row) * KP2 + kbA * 64 + c * 8) * 2);
    }
#pragma unroll
    for (int u = 0; u < 8; ++u) {          // B: 1024 16B segs
        int seg = tid + u * NTHR;
        int row = seg >> 3, c = seg & 7;
        uint32_t off = row * 128 + c * 16;
        cp_async16(sB + SWZ(off),
                   (const char*)g_B2 + ((size_t)(n0 + row) * KP2 + kbB * 64 + c * 8) * 2);
    }
}

// one k16 step: 8 ldsm + 32 mma (declares its own fragment regs)
#define DO_KS(ks)                                                                   \
    do {                                                                            \
        uint32_t af[4][4];                                                          \
        uint32_t bf[4][4];                                                          \
        _Pragma("unroll")                                                           \
        for (int i = 0; i < 4; ++i) {                                               \
            uint32_t off = (uint32_t)(a_row + i * 16) * 128 + ((ks) * 2 + a_chunk) * 16; \
            ldsm_x4(af[i], sA + SWZ(off));                                          \
        }                                                                           \
        _Pragma("unroll")                                                           \
        for (int jj = 0; jj < 4; ++jj) {                                            \
            uint32_t off = (uint32_t)(b_row + jj * 16) * 128 + ((ks) * 2 + b_chunk) * 16; \
            ldsm_x4(bf[jj], sB + SWZ(off));                                         \
        }                                                                           \
        _Pragma("unroll")                                                           \
        for (int i = 0; i < 4; ++i)                                                 \
            _Pragma("unroll")                                                       \
            for (int j = 0; j < 8; ++j)                                             \
                mma_bf16(acc[i][j], af[i], &bf[j >> 1][(j & 1) * 2]);               \
    } while (0)

__global__ void __launch_bounds__(NTHR, 2)
gemm_mma_kernel(float* __restrict__ logit) {
    extern __shared__ char dynsmem[];
    const int tid = threadIdx.x;
    const int lane = tid & 31;
    const int wid = tid >> 5;
    const int warp_m = wid >> 1;        // 0..1 (64 rows)
    const int warp_n = wid & 1;         // 0..1 (64 cols)
    const int m0 = blockIdx.x * BM;     // m fastest -> B reuse in L2
    const int n0 = blockIdx.y * BN;

    uint32_t tile0 = (smem_u32(dynsmem) + 127) & ~127u;

    // ldmatrix per-lane addressing
    const int a_row   = warp_m * 64 + (lane & 15);
    const int a_chunk = lane >> 4;                          // 0/1 -> k8 half
    const int bg      = lane >> 3;                          // 0..3
    const int b_row   = warp_n * 64 + ((bg >> 1) << 3) + (lane & 7);
    const int b_chunk = bg & 1;

    float acc[4][8][4];
#pragma unroll
    for (int i = 0; i < 4; i++)
#pragma unroll
        for (int j = 0; j < 8; j++)
#pragma unroll
            for (int q = 0; q < 4; q++) acc[i][j][q] = 0.f;

    load_stage(tile0 + 0 * STAGE, m0, n0, 0, tid); cp_commit();
    load_stage(tile0 + 1 * STAGE, m0, n0, 1, tid); cp_commit();

    int stage_c = 0;     // consumer stage
    int stage_p = 2;     // producer stage (kt+2)
#pragma unroll 1
    for (int kt = 0; kt < NKI; ++kt) {
        cp_wait<1>();                 // my stage-kt copies done
        __syncthreads();              // all copies visible; stage (kt+2)%3 free

        uint32_t sA = tile0 + stage_c * STAGE;
        uint32_t sB = sA + 16384;

        DO_KS(0);                     // start tensor work immediately

        int kn = kt + 2;              // issue next-stage loads in ks0's shadow
        if (kn < NKI) load_stage(tile0 + stage_p * STAGE, m0, n0, kn, tid);
        cp_commit();

        DO_KS(1);
        DO_KS(2);
        DO_KS(3);

        stage_c = (stage_c + 1 == NSTAGE) ? 0 : stage_c + 1;
        stage_p = (stage_p + 1 == NSTAGE) ? 0 : stage_p + 1;
    }

    // ---------------- epilogue: store logits + fused softmax partials (64-wide)
    const int n_base = n0 + warp_n * 64;
    const int t64 = n_base >> 6;

#pragma unroll
    for (int i = 0; i < 4; ++i) {
#pragma unroll
        for (int half = 0; half < 2; ++half) {
            const int gm = m0 + warp_m * 64 + i * 16 + (lane >> 2) + half * 8;
            float v[16];
#pragma unroll
            for (int j = 0; j < 8; ++j) {
                v[2 * j]     = acc[i][j][half * 2];
                v[2 * j + 1] = acc[i][j][half * 2 + 1];
            }
            float* p = logit + (size_t)gm * N_VOCAB + n_base;
#pragma unroll
            for (int j = 0; j < 8; ++j)
                *(float2*)(p + j * 8 + (lane & 3) * 2) = make_float2(v[2 * j], v[2 * j + 1]);

            float mx = v[0];
#pragma unroll
            for (int q = 1; q < 16; ++q) mx = fmaxf(mx, v[q]);
            mx = fmaxf(mx, __shfl_xor_sync(0xffffffffu, mx, 1));
            mx = fmaxf(mx, __shfl_xor_sync(0xffffffffu, mx, 2));

            float S = 0.f, b0 = 0.f, b3 = 0.f, b4 = 0.f, b5 = 0.f;
#pragma unroll
            for (int j = 0; j < 8; ++j) {
                float e0 = __expf(v[2 * j] - mx);
                float e1 = __expf(v[2 * j + 1] - mx);
                float s2 = e0 + e1;
                S += s2;
                b0 += e1;                    // col bit0 = odd element
                if (j & 1) b3 += s2;         // col bit3 = j&1
                if (j & 2) b4 += s2;         // col bit4 = j&2
                if (j & 4) b5 += s2;         // col bit5 = j&4
            }
            float b1 = (lane & 1) ? S : 0.f;     // col bit1
            float b2 = (lane & 2) ? S : 0.f;     // col bit2

#pragma unroll
            for (int o = 1; o <= 2; o <<= 1) {
                S  += __shfl_xor_sync(0xffffffffu, S, o);
                b0 += __shfl_xor_sync(0xffffffffu, b0, o);
                b1 += __shfl_xor_sync(0xffffffffu, b1, o);
                b2 += __shfl_xor_sync(0xffffffffu, b2, o);
                b3 += __shfl_xor_sync(0xffffffffu, b3, o);
                b4 += __shfl_xor_sync(0xffffffffu, b4, o);
                b5 += __shfl_xor_sync(0xffffffffu, b5, o);
            }

            if ((lane & 3) == 0) {
                int idx = gm * NT64 + t64;
                g_pmax[idx] = mx;
                g_psum[idx] = S;
                float* pn = g_pnum + (size_t)idx * 6;
                pn[0] = b5;   // logit_w k=9  (bit 5)
                pn[1] = b4;   // k=10
                pn[2] = b3;   // k=11
                pn[3] = b2;   // k=12
                pn[4] = b1;   // k=13
                pn[5] = b0;   // k=14 (bit 0)
            }
        }
    }
}

// ---------------------------------------------------------------- reduce
__global__ void reduce_kernel(float* __restrict__ logit_w) {
    int row = blockIdx.x;
    int lane = threadIdx.x;

    float lmax = -3.402823466e38f;
    for (int t = lane; t < NT64; t += 32)
        lmax = fmaxf(lmax, g_pmax[row * NT64 + t]);
#pragma unroll
    for (int o = 16; o >= 1; o >>= 1)
        lmax = fmaxf(lmax, __shfl_xor_sync(0xffffffffu, lmax, o));

    float tot = 0.f;
    float num[NBITS];
#pragma unroll
    for (int k = 0; k < NBITS; k++) num[k] = 0.f;

    for (int t = lane; t < NT64; t += 32) {
        int idx = row * NT64 + t;
        float w = __expf(g_pmax[idx] - lmax);
        float Sw = g_psum[idx] * w;
        tot += Sw;
        int vb = t << 6;                       // tile vocab base (high 9 bits constant)
#pragma unroll
        for (int k = 0; k < 9; k++)
            if ((vb >> (14 - k)) & 1) num[k] += Sw;
        const float* pn = g_pnum + (size_t)idx * 6;
        num[9]  += pn[0] * w;
        num[10] += pn[1] * w;
        num[11] += pn[2] * w;
        num[12] += pn[3] * w;
        num[13] += pn[4] * w;
        num[14] += pn[5] * w;
    }
#pragma unroll
    for (int o = 16; o >= 1; o >>= 1) {
        tot += __shfl_xor_sync(0xffffffffu, tot, o);
#pragma unroll
        for (int k = 0; k < NBITS; k++)
            num[k] += __shfl_xor_sync(0xffffffffu, num[k], o);
    }

    if (lane == 0) {
#pragma unroll
        for (int k = 0; k < NBITS; k++)
            logit_w[row * NBITS + k] = (2.f * num[k] - tot) / tot;
    }
}

// ---------------------------------------------------------------- launch
extern "C" void kernel_launch(void* const* d_in, const int* in_sizes, int n_in,
                              void* d_out, int out_size) {
    const int*   ids        = (const int*)d_in[0];
    const float* tensor     = (const float*)d_in[1];
    const float* weight     = (const float*)d_in[2];
    const float* weight_bit = (const float*)d_in[3];

    float* out     = (float*)d_out;
    float* id_emb  = out;
    float* bit_emb = out + 4194304;
    float* logit   = out + 8388608;
    float* logit_w = out + 8388608 + 131072000;

    cudaFuncSetAttribute(gemm_mma_kernel, cudaFuncAttributeMaxDynamicSharedMemorySize, DSMEM);

    prep_kernel<<<40192, 256>>>(tensor, weight, weight_bit, ids, id_emb, bit_emb);
    gemm_mma_kernel<<<dim3(M_TOTAL / BM, N_VOCAB / BN), NTHR, DSMEM>>>(logit);
    reduce_kernel<<<M_TOTAL, 32>>>(logit_w);
}